// round 12
// baseline (speedup 1.0000x reference)
#include <cuda_runtime.h>
#include <cuda_bf16.h>
#include <math.h>
#include <stdint.h>

// ---------------- problem dims (fixed) ----------------
#define T_TOK  2048
#define HDIM   1024
#define IDIM   2816
#define NEXP   8
#define NASSIGN 4096
#define NTMAX  48
#define APAD   (NASSIGN + 128)

#define WELEMS (NEXP * HDIM * IDIM)

// ---------------- device scratch (static globals, allowed) ----------------
__device__ __nv_bfloat16 g_xg_hi[APAD * HDIM];
__device__ __nv_bfloat16 g_xg_lo[APAD * HDIM];
__device__ __nv_bfloat16 g_act_hi[(size_t)APAD * IDIM];
__device__ __nv_bfloat16 g_act_lo[(size_t)APAD * IDIM];
__device__ float g_y[(size_t)APAD * HDIM];        // act@Wd^T fp32 (unweighted)
__device__ __nv_bfloat16 g_wgt_hi[WELEMS], g_wgt_lo[WELEMS];   // w_gate^T [E][I][H]
__device__ __nv_bfloat16 g_wut_hi[WELEMS], g_wut_lo[WELEMS];   // w_up^T   [E][I][H]
__device__ __nv_bfloat16 g_wdt_hi[WELEMS], g_wdt_lo[WELEMS];   // w_down^T [E][H][I]

__device__ int   g_perm_tok[NASSIGN];
__device__ float g_perm_w[NASSIGN];
__device__ int   g_pos[NASSIGN];
__device__ int   g_tok_eid[NASSIGN];
__device__ float g_tok_w[NASSIGN];
__device__ int   g_counts[NEXP];
__device__ int   g_off[NEXP + 1];
__device__ int   g_cursor[NEXP];
__device__ int   g_te[NTMAX], g_tr0[NTMAX];
__device__ int   g_nt;

// ---------------- PTX helpers (portable sm_80+ subset) ----------------
__device__ __forceinline__ uint32_t smem_u32(const void* p) {
    uint32_t a;
    asm("{ .reg .u64 t; cvta.to.shared.u64 t, %1; cvt.u32.u64 %0, t; }" : "=r"(a) : "l"(p));
    return a;
}
__device__ __forceinline__ void cpasync16(uint32_t dst, const void* src) {
    asm volatile("cp.async.cg.shared.global [%0], [%1], 16;" :: "r"(dst), "l"(src));
}
__device__ __forceinline__ void cp_commit() {
    asm volatile("cp.async.commit_group;" ::: "memory");
}
__device__ __forceinline__ void cp_wait2() {
    asm volatile("cp.async.wait_group 2;" ::: "memory");
}
__device__ __forceinline__ void ldsm4(uint32_t* r, uint32_t a) {
    asm volatile("ldmatrix.sync.aligned.m8n8.x4.shared.b16 {%0,%1,%2,%3}, [%4];"
                 : "=r"(r[0]), "=r"(r[1]), "=r"(r[2]), "=r"(r[3]) : "r"(a));
}
__device__ __forceinline__ void mma16816(float* c, const uint32_t* a, uint32_t b0, uint32_t b1) {
    asm volatile(
        "mma.sync.aligned.m16n8k16.row.col.f32.bf16.bf16.f32 "
        "{%0,%1,%2,%3}, {%4,%5,%6,%7}, {%8,%9}, {%0,%1,%2,%3};"
        : "+f"(c[0]), "+f"(c[1]), "+f"(c[2]), "+f"(c[3])
        : "r"(a[0]), "r"(a[1]), "r"(a[2]), "r"(a[3]), "r"(b0), "r"(b1));
}
// 32B rows (KC=16 bf16), 2x16B chunks, XOR swizzle ch ^= (row>>2)&1:
// 8 consecutive rows at fixed ch hit 8 distinct 16B slots of each 128B segment.
__device__ __forceinline__ uint32_t sw32(int row, int ch) {
    return (uint32_t)(row * 32 + (((ch ^ (row >> 2)) & 1) << 4));
}

// ---------------- small kernels ----------------
__global__ void k_init() {
    int i = threadIdx.x;
    if (i < NEXP) { g_counts[i] = 0; g_cursor[i] = 0; }
}

__global__ void k_router(const float* __restrict__ x, const float* __restrict__ gw,
                         float* __restrict__ out_logits, int write_logits) {
    int warp = threadIdx.x >> 5, lane = threadIdx.x & 31;
    int t = blockIdx.x * 8 + warp;
    const float* xt = x + (size_t)t * HDIM;
    float xr[32];
#pragma unroll
    for (int i = 0; i < 32; i++) xr[i] = xt[i * 32 + lane];
    float lg[NEXP];
#pragma unroll
    for (int e = 0; e < NEXP; e++) {
        const float* ge = gw + e * HDIM;
        float s = 0.f;
#pragma unroll
        for (int i = 0; i < 32; i++) s += xr[i] * ge[i * 32 + lane];
#pragma unroll
        for (int o = 16; o > 0; o >>= 1) s += __shfl_xor_sync(0xffffffffu, s, o);
        lg[e] = s;
    }
    if (lane == 0) {
        if (write_logits) {
#pragma unroll
            for (int e = 0; e < NEXP; e++) out_logits[t * NEXP + e] = lg[e];
        }
        int a = 0;
#pragma unroll
        for (int e = 1; e < NEXP; e++) if (lg[e] > lg[a]) a = e;
        int b = (a == 0) ? 1 : 0;
#pragma unroll
        for (int e = 0; e < NEXP; e++) if (e != a && lg[e] > lg[b]) b = e;
        float wa = 1.f / (1.f + expf(lg[b] - lg[a]));
        g_tok_eid[2 * t]     = a; g_tok_w[2 * t]     = wa;
        g_tok_eid[2 * t + 1] = b; g_tok_w[2 * t + 1] = 1.f - wa;
        atomicAdd(&g_counts[a], 1);
        atomicAdd(&g_counts[b], 1);
    }
}

__global__ void k_scan() {
    if (threadIdx.x != 0) return;
    int off = 0;
    for (int e = 0; e < NEXP; e++) { g_off[e] = off; g_cursor[e] = off; off += g_counts[e]; }
    g_off[NEXP] = off;
    int nt = 0;
    for (int e = 0; e < NEXP; e++)
        for (int r = 0; r < g_counts[e]; r += 128) { g_te[nt] = e; g_tr0[nt] = g_off[e] + r; nt++; }
    g_nt = nt;
}

__global__ void k_scatter() {
    int t = blockIdx.x * blockDim.x + threadIdx.x;
    if (t >= T_TOK) return;
#pragma unroll
    for (int k = 0; k < 2; k++) {
        int e = g_tok_eid[2 * t + k];
        int pos = atomicAdd(&g_cursor[e], 1);
        g_perm_tok[pos] = t;
        g_perm_w[pos]   = g_tok_w[2 * t + k];
        g_pos[2 * t + k] = pos;
    }
}

__global__ void k_gather(const float* __restrict__ x) {
    int pos = blockIdx.x;
    int tok = g_perm_tok[pos];
    int i = threadIdx.x * 4;
    float4 v = *(const float4*)(x + (size_t)tok * HDIM + i);
    size_t o = (size_t)pos * HDIM + i;
    float vv[4] = { v.x, v.y, v.z, v.w };
#pragma unroll
    for (int j = 0; j < 4; j++) {
        __nv_bfloat16 h = __float2bfloat16(vv[j]);
        g_xg_hi[o + j] = h;
        g_xg_lo[o + j] = __float2bfloat16(vv[j] - __bfloat162float(h));
    }
}

// transpose W[e][K][N] fp32 -> hi/lo bf16 [e][N][K] (globals only in device code)
template<int SEL>
__global__ void k_transpose(const float* __restrict__ W) {
    constexpr int K = (SEL == 2) ? IDIM : HDIM;
    constexpr int N = (SEL == 2) ? HDIM : IDIM;
    __nv_bfloat16* hi = (SEL == 0) ? g_wgt_hi : (SEL == 1) ? g_wut_hi : g_wdt_hi;
    __nv_bfloat16* lo = (SEL == 0) ? g_wgt_lo : (SEL == 1) ? g_wut_lo : g_wdt_lo;

    __shared__ float tile[32][33];
    int e = blockIdx.z;
    const float* We = W + (size_t)e * K * N;
    size_t ob = (size_t)e * K * N;
    int n0 = blockIdx.x * 32, k0 = blockIdx.y * 32;
    int tx = threadIdx.x, ty = threadIdx.y;
#pragma unroll
    for (int i = 0; i < 4; i++)
        tile[ty * 4 + i][tx] = We[(size_t)(k0 + ty * 4 + i) * N + n0 + tx];
    __syncthreads();
#pragma unroll
    for (int i = 0; i < 4; i++) {
        int r = ty * 4 + i;
        float v = tile[tx][r];
        __nv_bfloat16 h = __float2bfloat16(v);
        size_t o = ob + (size_t)(n0 + r) * K + k0 + tx;
        hi[o] = h;
        lo[o] = __float2bfloat16(v - __bfloat162float(h));
    }
}

// ============ GEMM1 fused: G,U = X@Wg^T, X@Wu^T; act = silu(G)*U -> bf16 hi/lo =====
// BM=128, BN=64 (both G and U), KC=16, 3-stage cp.async, 48KB STATIC smem, 256 thr.
// stage (16KB): [Ah 4K | Al 4K | GH 2K | GL 2K | UH 2K | UL 2K]
#define F_AH 0
#define F_AL 4096
#define F_GH 8192
#define F_GL 10240
#define F_UH 12288
#define F_UL 14336
#define F_SZ 16384

__global__ __launch_bounds__(256)
void k_gemm1f() {
    constexpr int NCH = HDIM / 16;   // 64
    __shared__ __align__(16) char smem[3 * F_SZ];   // 48KB static

    int bx = blockIdx.x;
    if (bx >= g_nt) return;
    int e = g_te[bx], row0 = g_tr0[bx], send = g_off[e + 1];
    int nblk = blockIdx.y * 64;
    int tid = threadIdx.x, lane = tid & 31, warp = tid >> 5;
    int wm = (warp >> 1) * 32, wn = (warp & 1) * 32;   // 4M x 2N warps, 32x32 each

    const __nv_bfloat16* pa_h = g_xg_hi + (size_t)row0 * HDIM;
    const __nv_bfloat16* pa_l = g_xg_lo + (size_t)row0 * HDIM;
    size_t eoff = ((size_t)e * IDIM + nblk) * HDIM;
    const __nv_bfloat16* pg_h = g_wgt_hi + eoff;
    const __nv_bfloat16* pg_l = g_wgt_lo + eoff;
    const __nv_bfloat16* pu_h = g_wut_hi + eoff;
    const __nv_bfloat16* pu_l = g_wut_lo + eoff;

    uint32_t sb = smem_u32(smem);

    auto issue = [&](int c, int st) {
        if (c < NCH) {
            int k0 = c << 4;
            uint32_t b = sb + (uint32_t)st * F_SZ;
            {   // A: 128 rows x 2 chunks (hi+lo)
                int row = tid >> 1, ch = tid & 1;
                uint32_t sw = sw32(row, ch);
                size_t go = (size_t)row * HDIM + k0 + ch * 8;
                cpasync16(b + F_AH + sw, pa_h + go);
                cpasync16(b + F_AL + sw, pa_l + go);
            }
            {   // B: 4 tiles x (64 rows x 2 chunks) = 512 ops over 2 rounds
#pragma unroll
                for (int r = 0; r < 2; r++) {
                    int idx = r * 256 + tid;
                    int tile = idx >> 7, within = idx & 127;
                    int row = within >> 1, ch = within & 1;
                    uint32_t sw = sw32(row, ch);
                    size_t go = (size_t)row * HDIM + k0 + ch * 8;
                    const __nv_bfloat16* src =
                        (tile == 0) ? pg_h : (tile == 1) ? pg_l : (tile == 2) ? pu_h : pu_l;
                    cpasync16(b + F_GH + tile * 2048 + sw, src + go);
                }
            }
        }
        cp_commit();
    };

    issue(0, 0); issue(1, 1); issue(2, 2);

    float ag[2][4][4], au[2][4][4];
#pragma unroll
    for (int i = 0; i < 2; i++)
#pragma unroll
        for (int j = 0; j < 4; j++)
#pragma unroll
            for (int k = 0; k < 4; k++) { ag[i][j][k] = 0.f; au[i][j][k] = 0.f; }

    int lrow = lane & 15, lch8 = lane >> 4;
    int st = 0;

    for (int c = 0; c < NCH; c++) {
        cp_wait2();
        __syncthreads();
        uint32_t base = sb + (uint32_t)st * F_SZ;
        uint32_t ah[2][4], al[2][4];
#pragma unroll
        for (int mt = 0; mt < 2; mt++) {
            uint32_t sw = sw32(wm + mt * 16 + lrow, lch8);
            ldsm4(ah[mt], base + F_AH + sw);
            ldsm4(al[mt], base + F_AL + sw);
        }
#pragma unroll
        for (int p = 0; p < 2; p++) {
            uint32_t sw = sw32(wn + p * 16 + lrow, lch8);
            uint32_t bh[4], bl[4];
            ldsm4(bh, base + F_GH + sw);
            ldsm4(bl, base + F_GL + sw);
#pragma unroll
            for (int mt = 0; mt < 2; mt++) {
                mma16816(ag[mt][2 * p],     ah[mt], bh[0], bh[2]);
                mma16816(ag[mt][2 * p],     al[mt], bh[0], bh[2]);
                mma16816(ag[mt][2 * p],     ah[mt], bl[0], bl[2]);
                mma16816(ag[mt][2 * p + 1], ah[mt], bh[1], bh[3]);
                mma16816(ag[mt][2 * p + 1], al[mt], bh[1], bh[3]);
                mma16816(ag[mt][2 * p + 1], ah[mt], bl[1], bl[3]);
            }
            ldsm4(bh, base + F_UH + sw);
            ldsm4(bl, base + F_UL + sw);
#pragma unroll
            for (int mt = 0; mt < 2; mt++) {
                mma16816(au[mt][2 * p],     ah[mt], bh[0], bh[2]);
                mma16816(au[mt][2 * p],     al[mt], bh[0], bh[2]);
                mma16816(au[mt][2 * p],     ah[mt], bl[0], bl[2]);
                mma16816(au[mt][2 * p + 1], ah[mt], bh[1], bh[3]);
                mma16816(au[mt][2 * p + 1], al[mt], bh[1], bh[3]);
                mma16816(au[mt][2 * p + 1], ah[mt], bl[1], bl[3]);
            }
        }
        __syncthreads();
        issue(c + 3, st);
        st = (st == 2) ? 0 : st + 1;
    }

    // fused SwiGLU epilogue: act = silu(g)*u -> hi/lo bf16
    int r_off = lane >> 2, c_off = (lane & 3) * 2;
#pragma unroll
    for (int mt = 0; mt < 2; mt++) {
#pragma unroll
        for (int h = 0; h < 2; h++) {
            int row = row0 + wm + mt * 16 + r_off + h * 8;
            if (row >= send) continue;
#pragma unroll
            for (int nt = 0; nt < 4; nt++) {
                float g0 = ag[mt][nt][2 * h + 0], g1 = ag[mt][nt][2 * h + 1];
                float u0 = au[mt][nt][2 * h + 0], u1 = au[mt][nt][2 * h + 1];
                float a0 = g0 * u0 / (1.f + __expf(-g0));
                float a1 = g1 * u1 / (1.f + __expf(-g1));
                __nv_bfloat16 h0 = __float2bfloat16(a0);
                __nv_bfloat16 h1 = __float2bfloat16(a1);
                __nv_bfloat16 l0 = __float2bfloat16(a0 - __bfloat162float(h0));
                __nv_bfloat16 l1 = __float2bfloat16(a1 - __bfloat162float(h1));
                size_t o = (size_t)row * IDIM + nblk + wn + nt * 8 + c_off;
                *reinterpret_cast<__nv_bfloat162*>(&g_act_hi[o]) = __nv_bfloat162(h0, h1);
                *reinterpret_cast<__nv_bfloat162*>(&g_act_lo[o]) = __nv_bfloat162(l0, l1);
            }
        }
    }
}

// ============ GEMM2: Y = act@Wd^T  (BM=128, BN=128, KC=16, 3-stage, 48KB static) ====
// stage (16KB): [Ah 4K | Al 4K | Bh 4K | Bl 4K]
#define D_AH 0
#define D_AL 4096
#define D_BH 8192
#define D_BL 12288
#define D_SZ 16384

__global__ __launch_bounds__(256)
void k_gemm2() {
    constexpr int NCH = IDIM / 16;   // 176
    __shared__ __align__(16) char smem[3 * D_SZ];   // 48KB static

    int bx = blockIdx.x;
    if (bx >= g_nt) return;
    int e = g_te[bx], row0 = g_tr0[bx], send = g_off[e + 1];
    int nblk = blockIdx.y * 128;
    int tid = threadIdx.x, lane = tid & 31, warp = tid >> 5;
    int wm = (warp >> 2) * 64, wn = (warp & 3) * 32;   // 2M x 4N warps, 64x32 each

    const __nv_bfloat16* pa_h = g_act_hi + (size_t)row0 * IDIM;
    const __nv_bfloat16* pa_l = g_act_lo + (size_t)row0 * IDIM;
    size_t eoff = ((size_t)e * HDIM + nblk) * IDIM;
    const __nv_bfloat16* pb_h = g_wdt_hi + eoff;
    const __nv_bfloat16* pb_l = g_wdt_lo + eoff;

    uint32_t sb = smem_u32(smem);

    auto issue = [&](int c, int st) {
        if (c < NCH) {
            int k0 = c << 4;
            uint32_t b = sb + (uint32_t)st * D_SZ;
            int row = tid >> 1, ch = tid & 1;
            uint32_t sw = sw32(row, ch);
            size_t go = (size_t)row * IDIM + k0 + ch * 8;
            cpasync16(b + D_AH + sw, pa_h + go);
            cpasync16(b + D_AL + sw, pa_l + go);
            cpasync16(b + D_BH + sw, pb_h + go);
            cpasync16(b + D_BL + sw, pb_l + go);
        }
        cp_commit();
    };

    issue(0, 0); issue(1, 1); issue(2, 2);

    float acc[4][4][4];
#pragma unroll
    for (int i = 0; i < 4; i++)
#pragma unroll
        for (int j = 0; j < 4; j++)
#pragma unroll
            for (int k = 0; k < 4; k++) acc[i][j][k] = 0.f;

    int lrow = lane & 15, lch8 = lane >> 4;
    int st = 0;

    for (int c = 0; c < NCH; c++) {
        cp_wait2();
        __syncthreads();
        uint32_t base = sb + (uint32_t)st * D_SZ;
        uint32_t ah[4][4], al[4][4];
#pragma unroll
        for (int mt = 0; mt < 4; mt++) {
            uint32_t sw = sw32(wm + mt * 16 + lrow, lch8);
            ldsm4(ah[mt], base + D_AH + sw);
            ldsm4(al[mt], base + D_AL + sw);
        }
#pragma unroll
        for (int p = 0; p < 2; p++) {
            uint32_t sw = sw32(wn + p * 16 + lrow, lch8);
            uint32_t bh[4], bl[4];
            ldsm4(bh, base + D_BH + sw);
            ldsm4(bl, base + D_BL + sw);
#pragma unroll
            for (int mt = 0; mt < 4; mt++) {
                mma16816(acc[mt][2 * p],     ah[mt], bh[0], bh[2]);
                mma16816(acc[mt][2 * p],     al[mt], bh[0], bh[2]);
                mma16816(acc[mt][2 * p],     ah[mt], bl[0], bl[2]);
                mma16816(acc[mt][2 * p + 1], ah[mt], bh[1], bh[3]);
                mma16816(acc[mt][2 * p + 1], al[mt], bh[1], bh[3]);
                mma16816(acc[mt][2 * p + 1], ah[mt], bl[1], bl[3]);
            }
        }
        __syncthreads();
        issue(c + 3, st);
        st = (st == 2) ? 0 : st + 1;
    }

    int r_off = lane >> 2, c_off = (lane & 3) * 2;
#pragma unroll
    for (int mt = 0; mt < 4; mt++) {
#pragma unroll
        for (int h = 0; h < 2; h++) {
            int row = row0 + wm + mt * 16 + r_off + h * 8;
            if (row >= send) continue;
            float* crow = g_y + (size_t)row * HDIM + nblk + wn + c_off;
#pragma unroll
            for (int nt = 0; nt < 4; nt++) {
                crow[nt * 8 + 0] = acc[mt][nt][2 * h + 0];
                crow[nt * 8 + 1] = acc[mt][nt][2 * h + 1];
            }
        }
    }
}

// ---------------- combine: out[t] = w0*y[p0] + w1*y[p1] ----------------
__global__ void k_combine(float* __restrict__ out) {
    int t = blockIdx.x;
    int h = threadIdx.x * 4;
    int p0 = g_pos[2 * t], p1 = g_pos[2 * t + 1];
    float w0 = g_perm_w[p0], w1 = g_perm_w[p1];
    float4 a = *(const float4*)&g_y[(size_t)p0 * HDIM + h];
    float4 b = *(const float4*)&g_y[(size_t)p1 * HDIM + h];
    float4 o;
    o.x = w0 * a.x + w1 * b.x;
    o.y = w0 * a.y + w1 * b.y;
    o.z = w0 * a.z + w1 * b.z;
    o.w = w0 * a.w + w1 * b.w;
    *(float4*)(out + (size_t)t * HDIM + h) = o;
}

// ---------------- launcher (no device-global symbols passed as args) ----------------
extern "C" void kernel_launch(void* const* d_in, const int* in_sizes, int n_in,
                              void* d_out, int out_size) {
    (void)in_sizes; (void)n_in;
    const float* x  = (const float*)d_in[0];
    const float* gw = (const float*)d_in[1];
    const float* wg = (const float*)d_in[2];
    const float* wu = (const float*)d_in[3];
    const float* wd = (const float*)d_in[4];
    float* out = (float*)d_out;

    int write_logits = (out_size >= T_TOK * HDIM + T_TOK * NEXP) ? 1 : 0;

    k_init<<<1, 32>>>();
    k_router<<<T_TOK / 8, 256>>>(x, gw, out + (size_t)T_TOK * HDIM, write_logits);
    k_scan<<<1, 1>>>();
    k_scatter<<<T_TOK / 256, 256>>>();
    k_gather<<<NASSIGN, 256>>>(x);
    // weight prep (hi/lo split + transpose to [E][N][K])
    k_transpose<0><<<dim3(IDIM / 32, HDIM / 32, NEXP), dim3(32, 8)>>>(wg);
    k_transpose<1><<<dim3(IDIM / 32, HDIM / 32, NEXP), dim3(32, 8)>>>(wu);
    k_transpose<2><<<dim3(HDIM / 32, IDIM / 32, NEXP), dim3(32, 8)>>>(wd);
    // fused gate+up GEMM with SwiGLU epilogue, then down GEMM
    k_gemm1f<<<dim3(40, IDIM / 64), 256>>>();
    k_gemm2<<<dim3(40, HDIM / 128), 256>>>();
    k_combine<<<T_TOK, 256>>>(out);
}